// round 13
// baseline (speedup 1.0000x reference)
#include <cuda_runtime.h>
#include <cuda_fp16.h>

#define THREADS 256
#define IT 4                      // i-rows per thread
#define I_TILE (THREADS * IT)     // 1024
#define J_TILE 64
#define MAXB 8192

__device__ double g_partial[MAXB];
__device__ int    g_done = 0;

__device__ __forceinline__ float fast_lg2(float x) {
    float r; asm("lg2.approx.f32 %0, %1;" : "=f"(r) : "f"(x)); return r;
}
// packed 2^x on two fp16 halves — ONE MUFU op for 2 pairs
__device__ __forceinline__ unsigned ex2_h2(unsigned u) {
    unsigned r; asm("ex2.approx.f16x2 %0, %1;" : "=r"(r) : "r"(u)); return r;
}
// arg = a XOR (signbits of s) per fp16 half: one LOP3 (immLut 0x78 = a^(b&c))
__device__ __forceinline__ unsigned sign2(unsigned a, unsigned s) {
    unsigned r;
    asm("lop3.b32 %0, %1, %2, 0x80008000, 0x78;" : "=r"(r) : "r"(a), "r"(s));
    return r;
}
__device__ __forceinline__ unsigned h2bits(__half2 h) {
    return *reinterpret_cast<unsigned*>(&h);
}
__device__ __forceinline__ __half2 bits2h(unsigned u) {
    return *reinterpret_cast<__half2*>(&u);
}

// Pair {i,j}: if ti<tj contribute logsig(pi-pj) = -ln2*lg2(1+2^(pjs-pis)).
// Dense blocks (J-range strictly above I-range): accumulate lg2(1+2^a),
// a = pjs-pis, UNCONDITIONALLY, then fix flipped pairs (tj<ti) via
// lg2(1+2^{-a}) = lg2(1+2^a) - a  =>  acc -= sum_{tj<ti} a = spre[m] - m*pis,
// with the j-tile sorted by target (fp32, exact) and spre its prefix sum.
// Band blocks (J-range inside I-range): full cross with fp16 sign logic; each
// unordered pair appears twice + diagonal contributes exactly 1.0 each:
// partial = 0.5*(sum - jcount). Count analytic: n(n-1)/2.
__global__ __launch_bounds__(THREADS, 4)
void rankloss_kernel(const float* __restrict__ P, const float* __restrict__ T,
                     float* __restrict__ out, int n, int NTI, int NTJ,
                     double inv_neg_count) {
    const int tid = threadIdx.x;
    const int nb  = gridDim.x;

    // decode linear block id -> (I, J) over upper-triangle band
    int b = blockIdx.x, I = 0, J = 0;
    {
        int rem = b;
        for (int ii = 0; ii < NTI; ++ii) {
            int jmin = (ii * I_TILE) / J_TILE;
            int cntI = NTJ - jmin;
            if (rem < cntI) { I = ii; J = jmin + rem; break; }
            rem -= cntI;
        }
    }
    const int I0 = I * I_TILE;
    const int J0 = J * J_TILE;
    const bool band = (J0 < I0 + I_TILE);

    __shared__ float    st[J_TILE];       // tj fp32 (sorted ascending)
    __shared__ float    sp[J_TILE];       // pjs fp32 (payload)
    __shared__ unsigned sjt16[J_TILE];    // half2(tj,tj)   (band path)
    __shared__ unsigned sjp16[J_TILE];    // half2(pjs,pjs) (both paths)
    __shared__ float    spre[J_TILE + 1]; // prefix sums of sorted sp
    __shared__ double   sred[THREADS];

    const float LOG2E = 1.4426950408889634f;
    const float INF   = __int_as_float(0x7F800000);

    if (tid < J_TILE) {
        int jg = J0 + tid;
        if (jg < n) { st[tid] = T[jg]; sp[tid] = P[jg] * LOG2E; }
        else        { st[tid] = INF;   sp[tid] = -INF; }  // pad: e -> 0 in band
    }

    float tiv[IT], piv[IT];
    #pragma unroll
    for (int r = 0; r < IT; ++r) {
        int ig = I0 + r * THREADS + tid;
        if (ig < n) { tiv[r] = T[ig]; piv[r] = P[ig] * LOG2E; }
        else        { tiv[r] = -INF;  piv[r] = INF; }  // pad: e -> 0 in band
    }
    const unsigned ti01 = h2bits(__floats2half2_rn(tiv[0], tiv[1]));
    const unsigned ti23 = h2bits(__floats2half2_rn(tiv[2], tiv[3]));
    const unsigned pi01 = h2bits(__floats2half2_rn(piv[0], piv[1]));
    const unsigned pi23 = h2bits(__floats2half2_rn(piv[2], piv[3]));
    __syncthreads();

    // Bitonic sort of the 64-entry tile by target (payload sp follows).
    for (int k = 2; k <= J_TILE; k <<= 1) {
        for (int half = k >> 1; half > 0; half >>= 1) {
            if (tid < J_TILE) {
                int partner = tid ^ half;
                if (partner > tid) {
                    bool up = ((tid & k) == 0);
                    float t1 = st[tid], t2 = st[partner];
                    if ((t1 > t2) == up) {
                        st[tid] = t2; st[partner] = t1;
                        float p1 = sp[tid], p2 = sp[partner];
                        sp[tid] = p2; sp[partner] = p1;
                    }
                }
            }
            __syncthreads();
        }
    }
    if (tid < J_TILE) {
        sjt16[tid] = h2bits(__floats2half2_rn(st[tid], st[tid]));
        sjp16[tid] = h2bits(__floats2half2_rn(sp[tid], sp[tid]));
    }
    if (tid == 0) {
        float run = 0.0f;
        spre[0] = 0.0f;
        for (int k = 0; k < J_TILE; ++k) {
            float v = sp[k];
            if (!(v > -INF)) v = 0.0f;   // pads never inside spre[0..m] anyway
            run += v; spre[k + 1] = run;
        }
    }
    __syncthreads();

    float acc = 0.0f;

    if (!band) {
        // m_r = #(tj < ti), exact fp32 comparisons on sorted st
        int mI[IT];
        #pragma unroll
        for (int r = 0; r < IT; ++r) {
            int m = 0;
            #pragma unroll
            for (int step = 32; step >= 1; step >>= 1)
                if (st[m + step - 1] < tiv[r]) m += step;
            mI[r] = m;
        }

        #pragma unroll 1
        for (int j = 0; j < J_TILE; j += 8) {
            float prod0 = 1.0f, prod1 = 1.0f, prod2 = 1.0f, prod3 = 1.0f;
            #pragma unroll
            for (int jj = 0; jj < 8; ++jj) {
                unsigned vp = sjp16[j + jj];   // broadcast LDS.32
                unsigned a01 = h2bits(__hsub2(bits2h(vp), bits2h(pi01)));
                unsigned a23 = h2bits(__hsub2(bits2h(vp), bits2h(pi23)));
                unsigned e01 = ex2_h2(a01);
                unsigned e23 = ex2_h2(a23);
                float2 f01 = __half22float2(bits2h(e01));
                float2 f23 = __half22float2(bits2h(e23));
                prod0 = fmaf(prod0, f01.x, prod0);
                prod1 = fmaf(prod1, f01.y, prod1);
                prod2 = fmaf(prod2, f23.x, prod2);
                prod3 = fmaf(prod3, f23.y, prod3);
            }
            acc += fast_lg2(prod0);
            acc += fast_lg2(prod1);
            acc += fast_lg2(prod2);
            acc += fast_lg2(prod3);
        }

        // linear correction per row: acc -= sum_{tj<ti} (pjs - pis)
        #pragma unroll
        for (int r = 0; r < IT; ++r)
            acc -= spre[mI[r]] - (float)mI[r] * piv[r];
    } else {
        #pragma unroll 1
        for (int j = 0; j < J_TILE; j += 8) {
            float prod0 = 1.0f, prod1 = 1.0f, prod2 = 1.0f, prod3 = 1.0f;
            #pragma unroll
            for (int jj = 0; jj < 8; ++jj) {
                unsigned vt = sjt16[j + jj];
                unsigned vp = sjp16[j + jj];
                // s = tj - ti (sign selects orientation), a = pjs - pis
                unsigned s01 = h2bits(__hsub2(bits2h(vt), bits2h(ti01)));
                unsigned s23 = h2bits(__hsub2(bits2h(vt), bits2h(ti23)));
                unsigned a01 = h2bits(__hsub2(bits2h(vp), bits2h(pi01)));
                unsigned a23 = h2bits(__hsub2(bits2h(vp), bits2h(pi23)));
                unsigned e01 = ex2_h2(sign2(a01, s01));
                unsigned e23 = ex2_h2(sign2(a23, s23));
                float2 f01 = __half22float2(bits2h(e01));
                float2 f23 = __half22float2(bits2h(e23));
                prod0 = fmaf(prod0, f01.x, prod0);
                prod1 = fmaf(prod1, f01.y, prod1);
                prod2 = fmaf(prod2, f23.x, prod2);
                prod3 = fmaf(prod3, f23.y, prod3);
            }
            acc += fast_lg2(prod0);
            acc += fast_lg2(prod1);
            acc += fast_lg2(prod2);
            acc += fast_lg2(prod3);
        }
    }

    // block reduction (fixed order -> deterministic)
    sred[tid] = (double)acc;
    __syncthreads();
    #pragma unroll
    for (int s = THREADS / 2; s > 0; s >>= 1) {
        if (tid < s) sred[tid] += sred[tid + s];
        __syncthreads();
    }
    if (tid == 0) {
        double bsum = sred[0];
        if (band) {
            int jcount = min(J_TILE, n - J0);       // diagonal elements hit
            bsum = 0.5 * (bsum - (double)jcount);   // remove diag, undo x2
        }
        g_partial[blockIdx.x] = bsum;
    }

    // last-block finalize (fixed order -> deterministic)
    __shared__ int is_last;
    if (tid == 0) {
        __threadfence();
        int prev = atomicAdd(&g_done, 1);
        is_last = (prev == nb - 1) ? 1 : 0;
    }
    __syncthreads();
    if (is_last) {
        __threadfence();
        double s = 0.0;
        for (int i = tid; i < nb; i += THREADS) s += g_partial[i];
        sred[tid] = s;
        __syncthreads();
        #pragma unroll
        for (int k = THREADS / 2; k > 0; k >>= 1) {
            if (tid < k) sred[tid] += sred[tid + k];
            __syncthreads();
        }
        if (tid == 0) {
            out[0] = (float)(sred[0] * inv_neg_count);
            g_done = 0;   // reset for next graph replay
        }
    }
}

extern "C" void kernel_launch(void* const* d_in, const int* in_sizes, int n_in,
                              void* d_out, int out_size) {
    const float* predictions = (const float*)d_in[0];
    const float* targets     = (const float*)d_in[1];
    const int n = in_sizes[0];

    const int NTI = (n + I_TILE - 1) / I_TILE;   // 8 for n=8192
    const int NTJ = (n + J_TILE - 1) / J_TILE;   // 128
    int nb = 0;
    for (int ii = 0; ii < NTI; ++ii) {
        int jmin = (ii * I_TILE) / J_TILE;
        nb += NTJ - jmin;                        // 576 for n=8192
    }
    const double count = 0.5 * (double)n * (double)(n - 1);
    const double inv_neg_count = -0.6931471805599453 / count;

    rankloss_kernel<<<nb, THREADS>>>(predictions, targets, (float*)d_out,
                                     n, NTI, NTJ, inv_neg_count);
}

// round 14
// speedup vs baseline: 1.0152x; 1.0152x over previous
#include <cuda_runtime.h>
#include <cuda_fp16.h>

#define THREADS 256
#define IT 4                      // i-rows per thread
#define I_TILE (THREADS * IT)     // 1024
#define J_TILE 64
#define MAXB 8192
#define MAXN 16384

__device__ double   g_partial[MAXB];
__device__ int      g_done = 0;
// per-tile sorted scratch (written by prep_kernel, read by rankloss_kernel)
__device__ float    g_srt_t[MAXN];                          // sorted targets (fp32)
__device__ unsigned g_srt_p16[MAXN];                        // half2(pjs,pjs), sorted
__device__ float    g_pre[(MAXN / J_TILE) * (J_TILE + 1)];  // per-tile prefix sums

__device__ __forceinline__ float fast_lg2(float x) {
    float r; asm("lg2.approx.f32 %0, %1;" : "=f"(r) : "f"(x)); return r;
}
__device__ __forceinline__ unsigned ex2_h2(unsigned u) {
    unsigned r; asm("ex2.approx.f16x2 %0, %1;" : "=r"(r) : "r"(u)); return r;
}
// arg = a XOR (signbits of s) per fp16 half: one LOP3 (immLut 0x78 = a^(b&c))
__device__ __forceinline__ unsigned sign2(unsigned a, unsigned s) {
    unsigned r;
    asm("lop3.b32 %0, %1, %2, 0x80008000, 0x78;" : "=r"(r) : "r"(a), "r"(s));
    return r;
}
__device__ __forceinline__ unsigned h2bits(__half2 h) {
    return *reinterpret_cast<unsigned*>(&h);
}
__device__ __forceinline__ __half2 bits2h(unsigned u) {
    return *reinterpret_cast<__half2*>(&u);
}

// ---------- prep: sort each 64-element j-tile by target, build prefix sums ----
__global__ __launch_bounds__(J_TILE)
void prep_kernel(const float* __restrict__ P, const float* __restrict__ T, int n) {
    const int tile = blockIdx.x;
    const int tid  = threadIdx.x;
    const float LOG2E = 1.4426950408889634f;
    const float INF   = __int_as_float(0x7F800000);

    __shared__ float st[J_TILE];
    __shared__ float sp[J_TILE];
    __shared__ float scan[J_TILE];

    int jg = tile * J_TILE + tid;
    if (jg < n) { st[tid] = T[jg]; sp[tid] = P[jg] * LOG2E; }
    else        { st[tid] = INF;   sp[tid] = -INF; }   // pad: sorts to end, e->0
    __syncthreads();

    // bitonic sort by target, payload sp follows
    for (int k = 2; k <= J_TILE; k <<= 1) {
        for (int half = k >> 1; half > 0; half >>= 1) {
            int partner = tid ^ half;
            if (partner > tid) {
                bool up = ((tid & k) == 0);
                float t1 = st[tid], t2 = st[partner];
                if ((t1 > t2) == up) {
                    st[tid] = t2; st[partner] = t1;
                    float p1 = sp[tid], p2 = sp[partner];
                    sp[tid] = p2; sp[partner] = p1;
                }
            }
            __syncthreads();
        }
    }

    // inclusive Hillis-Steele scan of sp (pads contribute 0)
    float v = (st[tid] < INF) ? sp[tid] : 0.0f;
    scan[tid] = v;
    __syncthreads();
    #pragma unroll
    for (int off = 1; off < J_TILE; off <<= 1) {
        float add = (tid >= off) ? scan[tid - off] : 0.0f;
        __syncthreads();
        scan[tid] += add;
        __syncthreads();
    }

    int og = tile * J_TILE + tid;
    g_srt_t[og]   = st[tid];
    g_srt_p16[og] = h2bits(__floats2half2_rn(sp[tid], sp[tid]));
    if (tid == 0) g_pre[tile * (J_TILE + 1)] = 0.0f;
    g_pre[tile * (J_TILE + 1) + tid + 1] = scan[tid];
}

// Pair {i,j}: if ti<tj contribute logsig(pi-pj) = -ln2*lg2(1+2^(pjs-pis)).
// Dense blocks: accumulate lg2(1+2^a), a = pjs-pis, UNCONDITIONALLY, then
// fix flipped pairs (tj<ti) via lg2(1+2^{-a}) = lg2(1+2^a) - a:
//   acc -= spre[m] - m*pis, m = #(tj<ti) on the target-sorted tile (exact fp32).
// Band blocks: full cross with fp16 sign selection; each unordered pair twice
// + diagonal exactly 1.0 each: partial = 0.5*(sum - jcount). Count: n(n-1)/2.
__global__ __launch_bounds__(THREADS, 4)
void rankloss_kernel(const float* __restrict__ P, const float* __restrict__ T,
                     float* __restrict__ out, int n, int NTI, int NTJ,
                     double inv_neg_count) {
    const int tid = threadIdx.x;
    const int nb  = gridDim.x;

    // decode linear block id -> (I, J) over upper-triangle band
    int b = blockIdx.x, I = 0, J = 0;
    {
        int rem = b;
        for (int ii = 0; ii < NTI; ++ii) {
            int jmin = (ii * I_TILE) / J_TILE;
            int cntI = NTJ - jmin;
            if (rem < cntI) { I = ii; J = jmin + rem; break; }
            rem -= cntI;
        }
    }
    const int I0 = I * I_TILE;
    const int J0 = J * J_TILE;
    const bool band = (J0 < I0 + I_TILE);

    __shared__ float    st[J_TILE];       // sorted tj (fp32, for search)
    __shared__ unsigned sjt16[J_TILE];    // half2(tj,tj)    (band path)
    __shared__ unsigned sjp16[J_TILE];    // half2(pjs,pjs)
    __shared__ float    spre[J_TILE + 1]; // prefix sums
    __shared__ double   sred[THREADS];

    const float LOG2E = 1.4426950408889634f;
    const float INF   = __int_as_float(0x7F800000);

    if (tid < J_TILE) {
        float t = g_srt_t[J0 + tid];
        st[tid]    = t;
        sjt16[tid] = h2bits(__floats2half2_rn(t, t));
        sjp16[tid] = g_srt_p16[J0 + tid];
    }
    if (tid < J_TILE + 1) spre[tid] = g_pre[(J0 / J_TILE) * (J_TILE + 1) + tid];

    float tiv[IT], piv[IT];
    #pragma unroll
    for (int r = 0; r < IT; ++r) {
        int ig = I0 + r * THREADS + tid;
        if (ig < n) { tiv[r] = T[ig]; piv[r] = P[ig] * LOG2E; }
        else        { tiv[r] = -INF;  piv[r] = INF; }  // pad: e -> 0, m = 0
    }
    const unsigned ti01 = h2bits(__floats2half2_rn(tiv[0], tiv[1]));
    const unsigned ti23 = h2bits(__floats2half2_rn(tiv[2], tiv[3]));
    const unsigned pi01 = h2bits(__floats2half2_rn(piv[0], piv[1]));
    const unsigned pi23 = h2bits(__floats2half2_rn(piv[2], piv[3]));
    __syncthreads();

    float acc = 0.0f;

    if (!band) {
        // m_r = #(tj < ti), exact fp32 comparisons on sorted st
        int mI[IT];
        #pragma unroll
        for (int r = 0; r < IT; ++r) {
            int m = 0;
            #pragma unroll
            for (int step = 32; step >= 1; step >>= 1)
                if (st[m + step - 1] < tiv[r]) m += step;
            mI[r] = m;
        }

        #pragma unroll 1
        for (int j = 0; j < J_TILE; j += 8) {
            float prod0 = 1.0f, prod1 = 1.0f, prod2 = 1.0f, prod3 = 1.0f;
            #pragma unroll
            for (int jj = 0; jj < 8; ++jj) {
                unsigned vp = sjp16[j + jj];   // broadcast LDS.32
                unsigned a01 = h2bits(__hsub2(bits2h(vp), bits2h(pi01)));
                unsigned a23 = h2bits(__hsub2(bits2h(vp), bits2h(pi23)));
                unsigned e01 = ex2_h2(a01);
                unsigned e23 = ex2_h2(a23);
                float2 f01 = __half22float2(bits2h(e01));
                float2 f23 = __half22float2(bits2h(e23));
                prod0 = fmaf(prod0, f01.x, prod0);
                prod1 = fmaf(prod1, f01.y, prod1);
                prod2 = fmaf(prod2, f23.x, prod2);
                prod3 = fmaf(prod3, f23.y, prod3);
            }
            acc += fast_lg2(prod0);
            acc += fast_lg2(prod1);
            acc += fast_lg2(prod2);
            acc += fast_lg2(prod3);
        }

        // linear correction per row: acc -= sum_{tj<ti} (pjs - pis)
        #pragma unroll
        for (int r = 0; r < IT; ++r)
            acc -= spre[mI[r]] - (float)mI[r] * piv[r];
    } else {
        #pragma unroll 1
        for (int j = 0; j < J_TILE; j += 8) {
            float prod0 = 1.0f, prod1 = 1.0f, prod2 = 1.0f, prod3 = 1.0f;
            #pragma unroll
            for (int jj = 0; jj < 8; ++jj) {
                unsigned vt = sjt16[j + jj];
                unsigned vp = sjp16[j + jj];
                // s = tj - ti (sign selects orientation), a = pjs - pis
                unsigned s01 = h2bits(__hsub2(bits2h(vt), bits2h(ti01)));
                unsigned s23 = h2bits(__hsub2(bits2h(vt), bits2h(ti23)));
                unsigned a01 = h2bits(__hsub2(bits2h(vp), bits2h(pi01)));
                unsigned a23 = h2bits(__hsub2(bits2h(vp), bits2h(pi23)));
                unsigned e01 = ex2_h2(sign2(a01, s01));
                unsigned e23 = ex2_h2(sign2(a23, s23));
                float2 f01 = __half22float2(bits2h(e01));
                float2 f23 = __half22float2(bits2h(e23));
                prod0 = fmaf(prod0, f01.x, prod0);
                prod1 = fmaf(prod1, f01.y, prod1);
                prod2 = fmaf(prod2, f23.x, prod2);
                prod3 = fmaf(prod3, f23.y, prod3);
            }
            acc += fast_lg2(prod0);
            acc += fast_lg2(prod1);
            acc += fast_lg2(prod2);
            acc += fast_lg2(prod3);
        }
    }

    // block reduction (fixed order -> deterministic)
    sred[tid] = (double)acc;
    __syncthreads();
    #pragma unroll
    for (int s = THREADS / 2; s > 0; s >>= 1) {
        if (tid < s) sred[tid] += sred[tid + s];
        __syncthreads();
    }
    if (tid == 0) {
        double bsum = sred[0];
        if (band) {
            int jcount = min(J_TILE, n - J0);       // diagonal elements hit
            bsum = 0.5 * (bsum - (double)jcount);   // remove diag, undo x2
        }
        g_partial[blockIdx.x] = bsum;
    }

    // last-block finalize (fixed order -> deterministic)
    __shared__ int is_last;
    if (tid == 0) {
        __threadfence();
        int prev = atomicAdd(&g_done, 1);
        is_last = (prev == nb - 1) ? 1 : 0;
    }
    __syncthreads();
    if (is_last) {
        __threadfence();
        double s = 0.0;
        for (int i = tid; i < nb; i += THREADS) s += g_partial[i];
        sred[tid] = s;
        __syncthreads();
        #pragma unroll
        for (int k = THREADS / 2; k > 0; k >>= 1) {
            if (tid < k) sred[tid] += sred[tid + k];
            __syncthreads();
        }
        if (tid == 0) {
            out[0] = (float)(sred[0] * inv_neg_count);
            g_done = 0;   // reset for next graph replay
        }
    }
}

extern "C" void kernel_launch(void* const* d_in, const int* in_sizes, int n_in,
                              void* d_out, int out_size) {
    const float* predictions = (const float*)d_in[0];
    const float* targets     = (const float*)d_in[1];
    const int n = in_sizes[0];

    const int NTI = (n + I_TILE - 1) / I_TILE;   // 8 for n=8192
    const int NTJ = (n + J_TILE - 1) / J_TILE;   // 128
    int nb = 0;
    for (int ii = 0; ii < NTI; ++ii) {
        int jmin = (ii * I_TILE) / J_TILE;
        nb += NTJ - jmin;                        // 576 for n=8192
    }
    const double count = 0.5 * (double)n * (double)(n - 1);
    const double inv_neg_count = -0.6931471805599453 / count;

    prep_kernel<<<NTJ, J_TILE>>>(predictions, targets, n);
    rankloss_kernel<<<nb, THREADS>>>(predictions, targets, (float*)d_out,
                                     n, NTI, NTJ, inv_neg_count);
}

// round 15
// speedup vs baseline: 1.1194x; 1.1026x over previous
#include <cuda_runtime.h>
#include <cuda_fp16.h>

#define THREADS 256
#define IT 4                      // i-rows per thread
#define I_TILE (THREADS * IT)     // 1024
#define J_TILE 32
#define MAXB 8192

__device__ double g_partial[MAXB];
__device__ int    g_done = 0;

__device__ __forceinline__ float fast_lg2(float x) {
    float r; asm("lg2.approx.f32 %0, %1;" : "=f"(r) : "f"(x)); return r;
}
// packed 2^x on two fp16 halves — ONE MUFU op for 2 pairs
__device__ __forceinline__ unsigned ex2_h2(unsigned u) {
    unsigned r; asm("ex2.approx.f16x2 %0, %1;" : "=r"(r) : "r"(u)); return r;
}
// arg = a XOR (signbits of s) per fp16 half: one LOP3 (immLut 0x78 = a^(b&c))
__device__ __forceinline__ unsigned sign2(unsigned a, unsigned s) {
    unsigned r;
    asm("lop3.b32 %0, %1, %2, 0x80008000, 0x78;" : "=r"(r) : "r"(a), "r"(s));
    return r;
}
__device__ __forceinline__ unsigned h2bits(__half2 h) {
    return *reinterpret_cast<unsigned*>(&h);
}
__device__ __forceinline__ __half2 bits2h(unsigned u) {
    return *reinterpret_cast<__half2*>(&u);
}

// Pair {i,j}: if ti<tj contribute logsig(pi-pj) = -ln2*lg2(1+2^(pjs-pis)),
// mirrored otherwise. Orientation: a = pjs - pis, s = tj - ti;
//   s > 0 (ti<tj): arg = a;  s < 0: arg = a ^ signbit = pis - pjs.
// All blocks run a full IxJ cross. Band blocks (J-range inside I-range) see
// each unordered pair twice (identical contribution) plus diagonal (exactly
// 1.0 each): partial = 0.5*(sum - jcount). Count analytic: n(n-1)/2.
__global__ __launch_bounds__(THREADS, 5)
void rankloss_kernel(const float* __restrict__ P, const float* __restrict__ T,
                     float* __restrict__ out, int n, int NTI, int NTJ,
                     double inv_neg_count) {
    const int tid = threadIdx.x;
    const int nb  = gridDim.x;

    // decode linear block id -> (I, J) over upper-triangle band
    int b = blockIdx.x, I = 0, J = 0;
    {
        int rem = b;
        for (int ii = 0; ii < NTI; ++ii) {
            int jmin = (ii * I_TILE) / J_TILE;
            int cntI = NTJ - jmin;
            if (rem < cntI) { I = ii; J = jmin + rem; break; }
            rem -= cntI;
        }
    }
    const int I0 = I * I_TILE;
    const int J0 = J * J_TILE;
    const bool band = (J0 < I0 + I_TILE);   // J-range inside I-range: weight 1/2

    __shared__ uint2  sjv[J_TILE];   // .x = half2(tj,tj), .y = half2(pjs,pjs)
    __shared__ double sred[THREADS];

    const float LOG2E = 1.4426950408889634f;
    const float INF   = __int_as_float(0x7F800000);

    if (tid < J_TILE) {
        int jg = J0 + tid;
        float tj, pj;
        if (jg < n) { tj = T[jg]; pj = P[jg] * LOG2E; }
        else        { tj = INF;   pj = -INF; }   // s=+inf (no flip), a=-inf -> e=0
        sjv[tid] = make_uint2(h2bits(__floats2half2_rn(tj, tj)),
                              h2bits(__floats2half2_rn(pj, pj)));
    }

    float tiv[IT], piv[IT];
    #pragma unroll
    for (int r = 0; r < IT; ++r) {
        int ig = I0 + r * THREADS + tid;
        if (ig < n) { tiv[r] = T[ig]; piv[r] = P[ig] * LOG2E; }
        else        { tiv[r] = -INF;  piv[r] = INF; }  // s=+inf, a=-inf -> e=0
    }
    const unsigned ti01 = h2bits(__floats2half2_rn(tiv[0], tiv[1]));
    const unsigned ti23 = h2bits(__floats2half2_rn(tiv[2], tiv[3]));
    const unsigned pi01 = h2bits(__floats2half2_rn(piv[0], piv[1]));
    const unsigned pi23 = h2bits(__floats2half2_rn(piv[2], piv[3]));
    __syncthreads();

    float acc = 0.0f;

    #pragma unroll 1
    for (int j = 0; j < J_TILE; j += 8) {
        float prod0 = 1.0f, prod1 = 1.0f, prod2 = 1.0f, prod3 = 1.0f;
        #pragma unroll
        for (int jj = 0; jj < 8; ++jj) {
            uint2 v = sjv[j + jj];             // one broadcast LDS.64
            // s = tj - ti  (sign selects orientation)
            unsigned s01 = h2bits(__hsub2(bits2h(v.x), bits2h(ti01)));
            unsigned s23 = h2bits(__hsub2(bits2h(v.x), bits2h(ti23)));
            // a = pjs - pis
            unsigned a01 = h2bits(__hsub2(bits2h(v.y), bits2h(pi01)));
            unsigned a23 = h2bits(__hsub2(bits2h(v.y), bits2h(pi23)));
            unsigned e01 = ex2_h2(sign2(a01, s01));
            unsigned e23 = ex2_h2(sign2(a23, s23));
            float2 f01 = __half22float2(bits2h(e01));
            float2 f23 = __half22float2(bits2h(e23));
            prod0 = fmaf(prod0, f01.x, prod0);
            prod1 = fmaf(prod1, f01.y, prod1);
            prod2 = fmaf(prod2, f23.x, prod2);
            prod3 = fmaf(prod3, f23.y, prod3);
        }
        acc += fast_lg2(prod0);
        acc += fast_lg2(prod1);
        acc += fast_lg2(prod2);
        acc += fast_lg2(prod3);
    }

    // block reduction (fixed order -> deterministic)
    sred[tid] = (double)acc;
    __syncthreads();
    #pragma unroll
    for (int s = THREADS / 2; s > 0; s >>= 1) {
        if (tid < s) sred[tid] += sred[tid + s];
        __syncthreads();
    }
    if (tid == 0) {
        double bsum = sred[0];
        if (band) {
            int jcount = min(J_TILE, n - J0);       // diagonal elements hit
            bsum = 0.5 * (bsum - (double)jcount);   // remove diag, undo x2
        }
        g_partial[blockIdx.x] = bsum;
    }

    // last-block finalize (fixed order -> deterministic)
    __shared__ int is_last;
    if (tid == 0) {
        __threadfence();
        int prev = atomicAdd(&g_done, 1);
        is_last = (prev == nb - 1) ? 1 : 0;
    }
    __syncthreads();
    if (is_last) {
        __threadfence();
        double s = 0.0;
        for (int i = tid; i < nb; i += THREADS) s += g_partial[i];
        sred[tid] = s;
        __syncthreads();
        #pragma unroll
        for (int k = THREADS / 2; k > 0; k >>= 1) {
            if (tid < k) sred[tid] += sred[tid + k];
            __syncthreads();
        }
        if (tid == 0) {
            out[0] = (float)(sred[0] * inv_neg_count);
            g_done = 0;   // reset for next graph replay
        }
    }
}

extern "C" void kernel_launch(void* const* d_in, const int* in_sizes, int n_in,
                              void* d_out, int out_size) {
    const float* predictions = (const float*)d_in[0];
    const float* targets     = (const float*)d_in[1];
    const int n = in_sizes[0];

    const int NTI = (n + I_TILE - 1) / I_TILE;   // 8 for n=8192
    const int NTJ = (n + J_TILE - 1) / J_TILE;   // 256
    int nb = 0;
    for (int ii = 0; ii < NTI; ++ii) {
        int jmin = (ii * I_TILE) / J_TILE;
        nb += NTJ - jmin;                        // 1152 for n=8192
    }
    const double count = 0.5 * (double)n * (double)(n - 1);
    const double inv_neg_count = -0.6931471805599453 / count;

    rankloss_kernel<<<nb, THREADS>>>(predictions, targets, (float*)d_out,
                                     n, NTI, NTJ, inv_neg_count);
}

// round 16
// speedup vs baseline: 1.1385x; 1.0171x over previous
#include <cuda_runtime.h>
#include <cuda_fp16.h>

#define THREADS 256
#define IT 4                      // i-rows per thread
#define I_TILE (THREADS * IT)     // 1024
#define J_TILE 64
#define MAXB 8192

__device__ double g_partial[MAXB];
__device__ int    g_done = 0;

__device__ __forceinline__ float fast_lg2(float x) {
    float r; asm("lg2.approx.f32 %0, %1;" : "=f"(r) : "f"(x)); return r;
}
__device__ __forceinline__ unsigned h2bits_f(float lo, float hi) {
    __half2 h = __floats2half2_rn(lo, hi);
    return *reinterpret_cast<unsigned*>(&h);
}

// Fully fused pair-op for 2 pairs (one i-pack x one j):
//   s   = tj - ti            (f16x2; sign selects orientation)
//   a   = pjs - pis          (f16x2)
//   arg = a ^ (s & 0x80008000)
//   e   = 2^arg              (one MUFU ex2.f16x2)
//   prodX = fma(prodX, eX, prodX)   (fp32, X = lo/hi half)
// One asm block, registers only — no pack/unpack glue, no local memory.
__device__ __forceinline__ void pair2(float& prodLo, float& prodHi,
                                      unsigned vt, unsigned ti,
                                      unsigned vp, unsigned pi) {
    asm("{\n\t"
        ".reg .b32 s, a;\n\t"
        ".reg .b16 lo, hi;\n\t"
        ".reg .f32 f0, f1;\n\t"
        "sub.rn.f16x2 s, %2, %3;\n\t"
        "sub.rn.f16x2 a, %4, %5;\n\t"
        "lop3.b32 a, a, s, 0x80008000, 0x78;\n\t"
        "ex2.approx.f16x2 a, a;\n\t"
        "mov.b32 {lo, hi}, a;\n\t"
        "cvt.f32.f16 f0, lo;\n\t"
        "cvt.f32.f16 f1, hi;\n\t"
        "fma.rn.f32 %0, %0, f0, %0;\n\t"
        "fma.rn.f32 %1, %1, f1, %1;\n\t"
        "}"
        : "+f"(prodLo), "+f"(prodHi)
        : "r"(vt), "r"(ti), "r"(vp), "r"(pi));
}

// Pair {i,j}: if ti<tj contribute logsig(pi-pj) = -ln2*lg2(1+2^(pjs-pis)),
// mirrored otherwise. All blocks run a full IxJ cross; band blocks (J-range
// inside I-range) see each unordered pair twice plus the diagonal (exactly
// 1.0 each): partial = 0.5*(sum - jcount). Count analytic: n(n-1)/2.
__global__ __launch_bounds__(THREADS, 4)
void rankloss_kernel(const float* __restrict__ P, const float* __restrict__ T,
                     float* __restrict__ out, int n, int NTI, int NTJ,
                     double inv_neg_count) {
    const int tid = threadIdx.x;
    const int nb  = gridDim.x;

    // decode linear block id -> (I, J) over upper-triangle band
    int b = blockIdx.x, I = 0, J = 0;
    {
        int rem = b;
        for (int ii = 0; ii < NTI; ++ii) {
            int jmin = (ii * I_TILE) / J_TILE;
            int cntI = NTJ - jmin;
            if (rem < cntI) { I = ii; J = jmin + rem; break; }
            rem -= cntI;
        }
    }
    const int I0 = I * I_TILE;
    const int J0 = J * J_TILE;
    const bool band = (J0 < I0 + I_TILE);   // J-range inside I-range: weight 1/2

    __shared__ uint2  sjv[J_TILE];   // .x = half2(tj,tj), .y = half2(pjs,pjs)
    __shared__ double sred[THREADS];

    const float LOG2E = 1.4426950408889634f;
    const float INF   = __int_as_float(0x7F800000);

    if (tid < J_TILE) {
        int jg = J0 + tid;
        float tj, pj;
        if (jg < n) { tj = T[jg]; pj = P[jg] * LOG2E; }
        else        { tj = INF;   pj = -INF; }   // s=+inf (no flip), a=-inf -> e=0
        sjv[tid] = make_uint2(h2bits_f(tj, tj), h2bits_f(pj, pj));
    }

    float tiv[IT], piv[IT];
    #pragma unroll
    for (int r = 0; r < IT; ++r) {
        int ig = I0 + r * THREADS + tid;
        if (ig < n) { tiv[r] = T[ig]; piv[r] = P[ig] * LOG2E; }
        else        { tiv[r] = -INF;  piv[r] = INF; }  // s=+inf, a=-inf -> e=0
    }
    const unsigned ti01 = h2bits_f(tiv[0], tiv[1]);
    const unsigned ti23 = h2bits_f(tiv[2], tiv[3]);
    const unsigned pi01 = h2bits_f(piv[0], piv[1]);
    const unsigned pi23 = h2bits_f(piv[2], piv[3]);
    __syncthreads();

    float acc = 0.0f;

    #pragma unroll 1
    for (int j = 0; j < J_TILE; j += 8) {
        float prod0 = 1.0f, prod1 = 1.0f, prod2 = 1.0f, prod3 = 1.0f;
        #pragma unroll
        for (int jj = 0; jj < 8; ++jj) {
            uint2 v = sjv[j + jj];             // one broadcast LDS.64
            pair2(prod0, prod1, v.x, ti01, v.y, pi01);
            pair2(prod2, prod3, v.x, ti23, v.y, pi23);
        }
        acc += fast_lg2(prod0);
        acc += fast_lg2(prod1);
        acc += fast_lg2(prod2);
        acc += fast_lg2(prod3);
    }

    // block reduction (fixed order -> deterministic)
    sred[tid] = (double)acc;
    __syncthreads();
    #pragma unroll
    for (int s = THREADS / 2; s > 0; s >>= 1) {
        if (tid < s) sred[tid] += sred[tid + s];
        __syncthreads();
    }
    if (tid == 0) {
        double bsum = sred[0];
        if (band) {
            int jcount = min(J_TILE, n - J0);       // diagonal elements hit
            bsum = 0.5 * (bsum - (double)jcount);   // remove diag, undo x2
        }
        g_partial[blockIdx.x] = bsum;
    }

    // last-block finalize (fixed order -> deterministic)
    __shared__ int is_last;
    if (tid == 0) {
        __threadfence();
        int prev = atomicAdd(&g_done, 1);
        is_last = (prev == nb - 1) ? 1 : 0;
    }
    __syncthreads();
    if (is_last) {
        __threadfence();
        double s = 0.0;
        for (int i = tid; i < nb; i += THREADS) s += g_partial[i];
        sred[tid] = s;
        __syncthreads();
        #pragma unroll
        for (int k = THREADS / 2; k > 0; k >>= 1) {
            if (tid < k) sred[tid] += sred[tid + k];
            __syncthreads();
        }
        if (tid == 0) {
            out[0] = (float)(sred[0] * inv_neg_count);
            g_done = 0;   // reset for next graph replay
        }
    }
}

extern "C" void kernel_launch(void* const* d_in, const int* in_sizes, int n_in,
                              void* d_out, int out_size) {
    const float* predictions = (const float*)d_in[0];
    const float* targets     = (const float*)d_in[1];
    const int n = in_sizes[0];

    const int NTI = (n + I_TILE - 1) / I_TILE;   // 8 for n=8192
    const int NTJ = (n + J_TILE - 1) / J_TILE;   // 128
    int nb = 0;
    for (int ii = 0; ii < NTI; ++ii) {
        int jmin = (ii * I_TILE) / J_TILE;
        nb += NTJ - jmin;                        // 576 for n=8192
    }
    const double count = 0.5 * (double)n * (double)(n - 1);
    const double inv_neg_count = -0.6931471805599453 / count;

    rankloss_kernel<<<nb, THREADS>>>(predictions, targets, (float*)d_out,
                                     n, NTI, NTJ, inv_neg_count);
}